// round 1
// baseline (speedup 1.0000x reference)
#include <cuda_runtime.h>
#include <cuda_bf16.h>
#include <mma.h>
#include <math.h>

using namespace nvcuda;
using tf32_t = wmma::precision::tf32;

// ---------------- problem constants ----------------
#define NQ   2048
#define DIM  1024
#define CDIM 768
#define HEADS 16
#define HD   64
#define MCTX 2048
#define DFF  4096

// ---------------- scratch (static device memory; no allocations) ----------------
__device__ float g_XQ[(size_t)NQ * DIM];
__device__ float g_KVN[(size_t)MCTX * CDIM];
__device__ float g_Q[(size_t)NQ * DIM];
__device__ float g_K[(size_t)MCTX * DIM];
__device__ float g_V[(size_t)MCTX * DIM];
__device__ float g_S[(size_t)HEADS * NQ * MCTX];   // 256 MB scores
__device__ float g_O[(size_t)NQ * DIM];
__device__ float g_X2[(size_t)NQ * DIM];
__device__ float g_HL[(size_t)NQ * DIM];
__device__ float g_H1[(size_t)NQ * DFF];

// ---------------- helpers ----------------
__device__ __forceinline__ float gelu_tanh(float x) {
    float x3 = x * x * x;
    return 0.5f * x * (1.0f + tanhf(0.7978845608028654f * (x + 0.044715f * x3)));
}

__device__ __forceinline__ float blockReduceSum(float v, float* red) {
    __syncthreads();  // protect shared buffer across repeated uses
    int lane = threadIdx.x & 31, wid = threadIdx.x >> 5;
    #pragma unroll
    for (int o = 16; o > 0; o >>= 1) v += __shfl_down_sync(0xffffffffu, v, o);
    if (lane == 0) red[wid] = v;
    __syncthreads();
    int nw = blockDim.x >> 5;
    v = (threadIdx.x < nw) ? red[threadIdx.x] : 0.0f;
    if (wid == 0) {
        #pragma unroll
        for (int o = 16; o > 0; o >>= 1) v += __shfl_down_sync(0xffffffffu, v, o);
    }
    return v;  // valid in thread 0
}

__device__ __forceinline__ float blockReduceMax(float v, float* red) {
    __syncthreads();
    int lane = threadIdx.x & 31, wid = threadIdx.x >> 5;
    #pragma unroll
    for (int o = 16; o > 0; o >>= 1) v = fmaxf(v, __shfl_down_sync(0xffffffffu, v, o));
    if (lane == 0) red[wid] = v;
    __syncthreads();
    int nw = blockDim.x >> 5;
    v = (threadIdx.x < nw) ? red[threadIdx.x] : -3.4e38f;
    if (wid == 0) {
        #pragma unroll
        for (int o = 16; o > 0; o >>= 1) v = fmaxf(v, __shfl_down_sync(0xffffffffu, v, o));
    }
    return v;
}

// ---------------- layernorm: one block per row ----------------
__global__ void ln_kernel(const float* __restrict__ in, const float* __restrict__ w,
                          const float* __restrict__ b, float* __restrict__ out, int D) {
    int row = blockIdx.x;
    const float* r = in + (size_t)row * D;
    float* o = out + (size_t)row * D;
    __shared__ float red[32];
    __shared__ float s_mean, s_inv;
    int tid = threadIdx.x;

    float s = 0.f;
    for (int i = tid; i < D; i += blockDim.x) s += r[i];
    s = blockReduceSum(s, red);
    if (tid == 0) s_mean = s / (float)D;
    __syncthreads();
    float mean = s_mean;

    float v = 0.f;
    for (int i = tid; i < D; i += blockDim.x) { float c = r[i] - mean; v += c * c; }
    v = blockReduceSum(v, red);
    if (tid == 0) s_inv = rsqrtf(v / (float)D + 1e-12f);
    __syncthreads();
    float inv = s_inv;

    for (int i = tid; i < D; i += blockDim.x)
        o[i] = (r[i] - mean) * inv * w[i] + b[i];
}

// ---------------- row softmax (in place): one block per row ----------------
__global__ void softmax_kernel(float* __restrict__ S, int L) {
    float* row = S + (size_t)blockIdx.x * L;
    __shared__ float red[32];
    __shared__ float s_max, s_inv;
    int tid = threadIdx.x;

    float m = -3.4e38f;
    for (int i = tid; i < L; i += blockDim.x) m = fmaxf(m, row[i]);
    m = blockReduceMax(m, red);
    if (tid == 0) s_max = m;
    __syncthreads();
    m = s_max;

    float s = 0.f;
    for (int i = tid; i < L; i += blockDim.x) {
        float e = __expf(row[i] - m);
        row[i] = e;
        s += e;
    }
    s = blockReduceSum(s, red);
    if (tid == 0) s_inv = 1.0f / s;
    __syncthreads();
    float inv = s_inv;

    for (int i = tid; i < L; i += blockDim.x) row[i] *= inv;
}

// ---------------- generic batched TF32 WMMA GEMM ----------------
// C[z] = epi( alpha * op(A[z]) @ B[z] )  row-major everything.
// TB=false : Bs[k][n] = B[k*ldb + n]        (NN)
// TB=true  : Bs[k][n] = B[n*ldb + k]        (NT, i.e. C = A @ B^T)
// EPI: 0 = alpha*acc (+bias if bias!=null)
//      1 = gelu_tanh(alpha*acc + bias)
//      2 = alpha*acc + bias + resid[row*ldc+col]
// Requires: M % 128 == 0, K % 32 == 0. N arbitrary (guarded).
template<bool TB, int EPI>
__global__ void __launch_bounds__(256)
gemm_tf32_kernel(const float* __restrict__ Ag, const float* __restrict__ Bg,
                 const float* __restrict__ bias, const float* __restrict__ Rg,
                 float* __restrict__ Cg,
                 int M, int N, int K, int lda, int ldb, int ldc,
                 long long sA, long long sB, long long sC, float alpha) {
    __shared__ float As[128][36];   // 128 x 32 (+4 pad)
    __shared__ float Bs[32][132];   // 32 x 128 (+4 pad)

    const float* A = Ag + (size_t)blockIdx.z * (size_t)sA;
    const float* B = Bg + (size_t)blockIdx.z * (size_t)sB;
    float* C = Cg + (size_t)blockIdx.z * (size_t)sC;

    const int bm0 = blockIdx.y * 128;
    const int bn0 = blockIdx.x * 128;
    const int tid = threadIdx.x;
    const int warp = tid >> 5, lane = tid & 31;
    const int wm = warp & 3;    // 4 warps along M, 32 rows each
    const int wn = warp >> 2;   // 2 warps along N, 64 cols each

    wmma::fragment<wmma::accumulator, 16, 16, 8, float> acc[2][4];
    #pragma unroll
    for (int i = 0; i < 2; i++)
        #pragma unroll
        for (int j = 0; j < 4; j++) wmma::fill_fragment(acc[i][j], 0.0f);

    const bool fullN = (bn0 + 128 <= N);

    for (int k0 = 0; k0 < K; k0 += 32) {
        // --- load A tile (always full: M%128==0, K%32==0), float4 ---
        #pragma unroll
        for (int t = 0; t < 4; t++) {
            int idx = tid + t * 256;         // 0..1023 -> 128 rows x 8 float4
            int r = idx >> 3;
            int c4 = idx & 7;
            float4 v = *(const float4*)(A + (size_t)(bm0 + r) * lda + k0 + c4 * 4);
            *(float4*)&As[r][c4 * 4] = v;
        }
        // --- load B tile ---
        if (!TB) {
            if (fullN) {
                #pragma unroll
                for (int t = 0; t < 4; t++) {
                    int idx = tid + t * 256;     // 32 rows x 32 float4
                    int r = idx >> 5;
                    int c4 = idx & 31;
                    float4 v = *(const float4*)(B + (size_t)(k0 + r) * ldb + bn0 + c4 * 4);
                    *(float4*)&Bs[r][c4 * 4] = v;
                }
            } else {
                for (int idx = tid; idx < 32 * 128; idx += 256) {
                    int r = idx >> 7, n = idx & 127;
                    Bs[r][n] = (bn0 + n < N) ? B[(size_t)(k0 + r) * ldb + bn0 + n] : 0.0f;
                }
            }
        } else {
            #pragma unroll
            for (int t = 0; t < 4; t++) {
                int idx = tid + t * 256;         // 128 n x 8 k-float4
                int n = idx >> 3;
                int k4 = idx & 7;
                float4 v;
                if (bn0 + n < N) v = *(const float4*)(B + (size_t)(bn0 + n) * ldb + k0 + k4 * 4);
                else v = make_float4(0.f, 0.f, 0.f, 0.f);
                Bs[k4 * 4 + 0][n] = v.x;
                Bs[k4 * 4 + 1][n] = v.y;
                Bs[k4 * 4 + 2][n] = v.z;
                Bs[k4 * 4 + 3][n] = v.w;
            }
        }
        __syncthreads();

        // --- compute ---
        #pragma unroll
        for (int kk = 0; kk < 32; kk += 8) {
            wmma::fragment<wmma::matrix_a, 16, 16, 8, tf32_t, wmma::row_major> af[2];
            wmma::fragment<wmma::matrix_b, 16, 16, 8, tf32_t, wmma::row_major> bf[4];
            #pragma unroll
            for (int i = 0; i < 2; i++) {
                wmma::load_matrix_sync(af[i], &As[wm * 32 + i * 16][kk], 36);
                #pragma unroll
                for (int t = 0; t < af[i].num_elements; t++)
                    af[i].x[t] = wmma::__float_to_tf32(af[i].x[t]);
            }
            #pragma unroll
            for (int j = 0; j < 4; j++) {
                wmma::load_matrix_sync(bf[j], &Bs[kk][wn * 64 + j * 16], 132);
                #pragma unroll
                for (int t = 0; t < bf[j].num_elements; t++)
                    bf[j].x[t] = wmma::__float_to_tf32(bf[j].x[t]);
            }
            #pragma unroll
            for (int i = 0; i < 2; i++)
                #pragma unroll
                for (int j = 0; j < 4; j++)
                    wmma::mma_sync(acc[i][j], af[i], bf[j], acc[i][j]);
        }
        __syncthreads();
    }

    // --- epilogue: stage each 16x16 frag in (reused) As, then fused epi ---
    float* st = &As[0][0] + warp * 384;   // 16 x 24 per warp, disjoint regions
    #pragma unroll
    for (int i = 0; i < 2; i++) {
        #pragma unroll
        for (int j = 0; j < 4; j++) {
            wmma::store_matrix_sync(st, acc[i][j], 24, wmma::mem_row_major);
            __syncwarp();
            int rb = bm0 + wm * 32 + i * 16;
            int cb = bn0 + wn * 64 + j * 16;
            #pragma unroll
            for (int e = 0; e < 8; e++) {
                int ei = lane + e * 32;          // 0..255
                int r = ei >> 4, c = ei & 15;
                int gc = cb + c;
                if (gc < N) {
                    float v = st[r * 24 + c] * alpha;
                    if (EPI == 0) {
                        if (bias) v += bias[gc];
                    } else if (EPI == 1) {
                        v = gelu_tanh(v + bias[gc]);
                    } else {
                        v += bias[gc] + Rg[(size_t)(rb + r) * ldc + gc];
                    }
                    C[(size_t)(rb + r) * ldc + gc] = v;
                }
            }
            __syncwarp();
        }
    }
}

// ---------------- launch ----------------
extern "C" void kernel_launch(void* const* d_in, const int* in_sizes, int n_in,
                              void* d_out, int out_size) {
    const float* x     = (const float*)d_in[0];
    const float* ctx   = (const float*)d_in[1];
    const float* wq    = (const float*)d_in[2];
    const float* bq    = (const float*)d_in[3];
    const float* wk    = (const float*)d_in[4];
    const float* bk    = (const float*)d_in[5];
    const float* wv    = (const float*)d_in[6];
    const float* bv    = (const float*)d_in[7];
    const float* wo    = (const float*)d_in[8];
    const float* bo    = (const float*)d_in[9];
    const float* w1    = (const float*)d_in[10];
    const float* b1    = (const float*)d_in[11];
    const float* w2    = (const float*)d_in[12];
    const float* b2    = (const float*)d_in[13];
    const float* qn_w  = (const float*)d_in[14];
    const float* qn_b  = (const float*)d_in[15];
    const float* kvn_w = (const float*)d_in[16];
    const float* kvn_b = (const float*)d_in[17];
    const float* pn_w  = (const float*)d_in[18];
    const float* pn_b  = (const float*)d_in[19];
    float* out = (float*)d_out;

    float *XQ, *KVN, *Q, *K, *V, *S, *O, *X2, *HL, *H1;
    cudaGetSymbolAddress((void**)&XQ,  g_XQ);
    cudaGetSymbolAddress((void**)&KVN, g_KVN);
    cudaGetSymbolAddress((void**)&Q,   g_Q);
    cudaGetSymbolAddress((void**)&K,   g_K);
    cudaGetSymbolAddress((void**)&V,   g_V);
    cudaGetSymbolAddress((void**)&S,   g_S);
    cudaGetSymbolAddress((void**)&O,   g_O);
    cudaGetSymbolAddress((void**)&X2,  g_X2);
    cudaGetSymbolAddress((void**)&HL,  g_HL);
    cudaGetSymbolAddress((void**)&H1,  g_H1);

    const float inv_scale = 1.0f / 8.0f;   // 1/sqrt(HD=64)

    // 1) pre-norms
    ln_kernel<<<NQ, 256>>>(x, qn_w, qn_b, XQ, DIM);
    ln_kernel<<<MCTX, 256>>>(ctx, kvn_w, kvn_b, KVN, CDIM);

    // 2) Q/K/V projections
    gemm_tf32_kernel<false, 0><<<dim3(DIM / 128, NQ / 128, 1), 256>>>(
        XQ, wq, bq, nullptr, Q, NQ, DIM, DIM, DIM, DIM, DIM, 0, 0, 0, 1.0f);
    gemm_tf32_kernel<false, 0><<<dim3(DIM / 128, MCTX / 128, 1), 256>>>(
        KVN, wk, bk, nullptr, K, MCTX, DIM, CDIM, CDIM, DIM, DIM, 0, 0, 0, 1.0f);
    gemm_tf32_kernel<false, 0><<<dim3(DIM / 128, MCTX / 128, 1), 256>>>(
        KVN, wv, bv, nullptr, V, MCTX, DIM, CDIM, CDIM, DIM, DIM, 0, 0, 0, 1.0f);

    // 3) scores: S[h] = (Q_h @ K_h^T) / 8   (batched over heads, NT)
    gemm_tf32_kernel<true, 0><<<dim3(MCTX / 128, NQ / 128, HEADS), 256>>>(
        Q, K, nullptr, nullptr, S, NQ, MCTX, HD, DIM, DIM, MCTX,
        (long long)HD, (long long)HD, (long long)NQ * MCTX, inv_scale);

    // 4) softmax over context dim
    softmax_kernel<<<HEADS * NQ, 256>>>(S, MCTX);

    // 5) O_h = S_h @ V_h   (batched over heads, NN, N=64)
    gemm_tf32_kernel<false, 0><<<dim3(1, NQ / 128, HEADS), 256>>>(
        S, V, nullptr, nullptr, O, NQ, HD, MCTX, MCTX, DIM, DIM,
        (long long)NQ * MCTX, (long long)HD, (long long)HD, 1.0f);

    // 6) output projection + residual: X2 = O @ wo + bo + x
    gemm_tf32_kernel<false, 2><<<dim3(DIM / 128, NQ / 128, 1), 256>>>(
        O, wo, bo, x, X2, NQ, DIM, DIM, DIM, DIM, DIM, 0, 0, 0, 1.0f);

    // 7) MLP block
    ln_kernel<<<NQ, 256>>>(X2, pn_w, pn_b, HL, DIM);
    gemm_tf32_kernel<false, 1><<<dim3(DFF / 128, NQ / 128, 1), 256>>>(
        HL, w1, b1, nullptr, H1, NQ, DFF, DIM, DIM, DFF, DFF, 0, 0, 0, 1.0f);
    gemm_tf32_kernel<false, 2><<<dim3(DIM / 128, NQ / 128, 1), 256>>>(
        H1, w2, b2, X2, out, NQ, DIM, DFF, DFF, DIM, DIM, 0, 0, 0, 1.0f);

    (void)in_sizes; (void)n_in; (void)out_size;
}

// round 2
// speedup vs baseline: 1.8085x; 1.8085x over previous
#include <cuda_runtime.h>
#include <cuda_bf16.h>
#include <mma.h>
#include <math.h>
#include <stdint.h>

using namespace nvcuda;
using tf32_t = wmma::precision::tf32;

// ---------------- problem constants ----------------
#define NQ   2048
#define DIM  1024
#define CDIM 768
#define HEADS 16
#define HD   64
#define MCTX 2048
#define DFF  4096

// ---------------- scratch (static device memory; no allocations) ----------------
__device__ float g_XQ[(size_t)NQ * DIM];
__device__ float g_KVN[(size_t)MCTX * CDIM];
__device__ float g_Q[(size_t)NQ * DIM];
__device__ float g_K[(size_t)MCTX * DIM];
__device__ float g_V[(size_t)MCTX * DIM];
__device__ float g_O[(size_t)NQ * DIM];
__device__ float g_X2[(size_t)NQ * DIM];
__device__ float g_HL[(size_t)NQ * DIM];
__device__ float g_H1[(size_t)NQ * DFF];

// ---------------- helpers ----------------
__device__ __forceinline__ float gelu_tanh(float x) {
    float x3 = x * x * x;
    return 0.5f * x * (1.0f + tanhf(0.7978845608028654f * (x + 0.044715f * x3)));
}

__device__ __forceinline__ uint32_t f2tf32(float f) {
    uint32_t u;
    asm("cvt.rna.tf32.f32 %0, %1;\n" : "=r"(u) : "f"(f));
    return u;
}

__device__ __forceinline__ void mma_tf32(float* d, const uint32_t* a, uint32_t b0, uint32_t b1) {
    asm volatile(
        "mma.sync.aligned.m16n8k8.row.col.f32.tf32.tf32.f32 "
        "{%0,%1,%2,%3}, {%4,%5,%6,%7}, {%8,%9}, {%0,%1,%2,%3};\n"
        : "+f"(d[0]), "+f"(d[1]), "+f"(d[2]), "+f"(d[3])
        : "r"(a[0]), "r"(a[1]), "r"(a[2]), "r"(a[3]), "r"(b0), "r"(b1));
}

__device__ __forceinline__ void cpa16(void* dst, const void* src) {
    uint32_t d = (uint32_t)__cvta_generic_to_shared(dst);
    asm volatile("cp.async.cg.shared.global [%0], [%1], 16;\n" :: "r"(d), "l"(src));
}
__device__ __forceinline__ void cpa_commit() { asm volatile("cp.async.commit_group;\n"); }
template<int N>
__device__ __forceinline__ void cpa_wait() { asm volatile("cp.async.wait_group %0;\n" :: "n"(N)); }

__device__ __forceinline__ float blockReduceSum(float v, float* red) {
    __syncthreads();
    int lane = threadIdx.x & 31, wid = threadIdx.x >> 5;
    #pragma unroll
    for (int o = 16; o > 0; o >>= 1) v += __shfl_down_sync(0xffffffffu, v, o);
    if (lane == 0) red[wid] = v;
    __syncthreads();
    int nw = blockDim.x >> 5;
    v = (threadIdx.x < nw) ? red[threadIdx.x] : 0.0f;
    if (wid == 0) {
        #pragma unroll
        for (int o = 16; o > 0; o >>= 1) v += __shfl_down_sync(0xffffffffu, v, o);
    }
    return v;
}

// ---------------- layernorm: one block per row ----------------
__global__ void ln_kernel(const float* __restrict__ in, const float* __restrict__ w,
                          const float* __restrict__ b, float* __restrict__ out, int D) {
    int row = blockIdx.x;
    const float* r = in + (size_t)row * D;
    float* o = out + (size_t)row * D;
    __shared__ float red[32];
    __shared__ float s_mean, s_inv;
    int tid = threadIdx.x;

    float s = 0.f;
    for (int i = tid; i < D; i += blockDim.x) s += r[i];
    s = blockReduceSum(s, red);
    if (tid == 0) s_mean = s / (float)D;
    __syncthreads();
    float mean = s_mean;

    float v = 0.f;
    for (int i = tid; i < D; i += blockDim.x) { float c = r[i] - mean; v += c * c; }
    v = blockReduceSum(v, red);
    if (tid == 0) s_inv = rsqrtf(v / (float)D + 1e-12f);
    __syncthreads();
    float inv = s_inv;

    for (int i = tid; i < D; i += blockDim.x)
        o[i] = (r[i] - mean) * inv * w[i] + b[i];
}

// ---------------- fused flash attention (TF32 mma.sync) ----------------
// grid: (NQ/128, HEADS), block 256 (8 warps). Each warp owns 16 query rows.
// KV chunk = 64 context tokens. Online softmax, P re-enters via smem as tf32.
#define KSTR 68
#define VSTR 72
#define PSTR 68
__global__ void __launch_bounds__(256)
flash_kernel(const float* __restrict__ Qg, const float* __restrict__ Kg,
             const float* __restrict__ Vg, float* __restrict__ Og) {
    extern __shared__ float sm[];
    float* Kt = sm;                       // 64 x KSTR
    float* Vt = sm + 64 * KSTR;           // 64 x VSTR
    float* Ps = sm + 64 * KSTR + 64 * VSTR; // 128 x PSTR

    const int h = blockIdx.y;
    const int q0 = blockIdx.x * 128;
    const int tid = threadIdx.x;
    const int w = tid >> 5, lane = tid & 31;
    const int lr = lane >> 2;      // 0..7
    const int cq = lane & 3;       // 0..3
    const int wr = w * 16;         // warp row base within tile

    // --- load Q fragments (pre-scaled by 1/sqrt(64)=0.125), convert to tf32 ---
    uint32_t qa[8][4];
    {
        const float* Qb = Qg + (size_t)(q0 + wr + lr) * DIM + h * HD;
        const float* Qb8 = Qb + 8 * DIM;
        #pragma unroll
        for (int ks = 0; ks < 8; ks++) {
            int c = ks * 8 + cq;
            qa[ks][0] = f2tf32(Qb [c]     * 0.125f);
            qa[ks][1] = f2tf32(Qb8[c]     * 0.125f);
            qa[ks][2] = f2tf32(Qb [c + 4] * 0.125f);
            qa[ks][3] = f2tf32(Qb8[c + 4] * 0.125f);
        }
    }

    float o[8][4];
    #pragma unroll
    for (int j = 0; j < 8; j++)
        #pragma unroll
        for (int e = 0; e < 4; e++) o[j][e] = 0.f;
    float m0 = -1e30f, m1 = -1e30f, l0 = 0.f, l1 = 0.f;

    for (int c0 = 0; c0 < MCTX; c0 += 64) {
        // --- load K,V chunk (64x64) into smem as tf32 bits ---
        #pragma unroll
        for (int t = 0; t < 4; t++) {
            int idx = tid + t * 256;           // 0..1023 float4 slots
            int r = idx >> 4, c4 = (idx & 15) * 4;
            const float4 kv = *(const float4*)(Kg + (size_t)(c0 + r) * DIM + h * HD + c4);
            float* kd = Kt + r * KSTR + c4;
            ((uint32_t*)kd)[0] = f2tf32(kv.x); ((uint32_t*)kd)[1] = f2tf32(kv.y);
            ((uint32_t*)kd)[2] = f2tf32(kv.z); ((uint32_t*)kd)[3] = f2tf32(kv.w);
            const float4 vv = *(const float4*)(Vg + (size_t)(c0 + r) * DIM + h * HD + c4);
            float* vd = Vt + r * VSTR + c4;
            ((uint32_t*)vd)[0] = f2tf32(vv.x); ((uint32_t*)vd)[1] = f2tf32(vv.y);
            ((uint32_t*)vd)[2] = f2tf32(vv.z); ((uint32_t*)vd)[3] = f2tf32(vv.w);
        }
        __syncthreads();

        // --- S = Q @ K^T (warp: 16 x 64) ---
        float s[8][4];
        #pragma unroll
        for (int j = 0; j < 8; j++)
            #pragma unroll
            for (int e = 0; e < 4; e++) s[j][e] = 0.f;

        #pragma unroll
        for (int ks = 0; ks < 8; ks++) {
            #pragma unroll
            for (int j = 0; j < 8; j++) {
                const float* kp = Kt + (j * 8 + lr) * KSTR + ks * 8 + cq;
                uint32_t b0 = ((const uint32_t*)kp)[0];
                uint32_t b1 = ((const uint32_t*)kp)[4];
                mma_tf32(s[j], qa[ks], b0, b1);
            }
        }

        // --- online softmax ---
        float mx0 = -1e30f, mx1 = -1e30f;
        #pragma unroll
        for (int j = 0; j < 8; j++) {
            mx0 = fmaxf(mx0, fmaxf(s[j][0], s[j][1]));
            mx1 = fmaxf(mx1, fmaxf(s[j][2], s[j][3]));
        }
        #pragma unroll
        for (int d = 1; d < 4; d <<= 1) {
            mx0 = fmaxf(mx0, __shfl_xor_sync(0xffffffffu, mx0, d));
            mx1 = fmaxf(mx1, __shfl_xor_sync(0xffffffffu, mx1, d));
        }
        float mn0 = fmaxf(m0, mx0), mn1 = fmaxf(m1, mx1);
        float cr0 = __expf(m0 - mn0), cr1 = __expf(m1 - mn1);
        float sum0 = 0.f, sum1 = 0.f;
        #pragma unroll
        for (int j = 0; j < 8; j++) {
            s[j][0] = __expf(s[j][0] - mn0); sum0 += s[j][0];
            s[j][1] = __expf(s[j][1] - mn0); sum0 += s[j][1];
            s[j][2] = __expf(s[j][2] - mn1); sum1 += s[j][2];
            s[j][3] = __expf(s[j][3] - mn1); sum1 += s[j][3];
        }
        #pragma unroll
        for (int d = 1; d < 4; d <<= 1) {
            sum0 += __shfl_xor_sync(0xffffffffu, sum0, d);
            sum1 += __shfl_xor_sync(0xffffffffu, sum1, d);
        }
        l0 = l0 * cr0 + sum0;
        l1 = l1 * cr1 + sum1;
        m0 = mn0; m1 = mn1;
        #pragma unroll
        for (int j = 0; j < 8; j++) {
            o[j][0] *= cr0; o[j][1] *= cr0;
            o[j][2] *= cr1; o[j][3] *= cr1;
        }

        // --- stash P (tf32) into warp-private smem slab ---
        {
            float* p0 = Ps + (wr + lr) * PSTR + 2 * cq;
            float* p1 = Ps + (wr + lr + 8) * PSTR + 2 * cq;
            #pragma unroll
            for (int j = 0; j < 8; j++) {
                ((uint32_t*)p0)[j * 8 + 0] = f2tf32(s[j][0]);
                ((uint32_t*)p0)[j * 8 + 1] = f2tf32(s[j][1]);
                ((uint32_t*)p1)[j * 8 + 0] = f2tf32(s[j][2]);
                ((uint32_t*)p1)[j * 8 + 1] = f2tf32(s[j][3]);
            }
        }
        __syncwarp();

        // --- O += P @ V ---
        #pragma unroll
        for (int ks = 0; ks < 8; ks++) {
            uint32_t a[4];
            const float* pa = Ps + (wr + lr) * PSTR + ks * 8 + cq;
            a[0] = ((const uint32_t*)pa)[0];
            a[1] = ((const uint32_t*)pa)[8 * PSTR];
            a[2] = ((const uint32_t*)pa)[4];
            a[3] = ((const uint32_t*)pa)[8 * PSTR + 4];
            #pragma unroll
            for (int j = 0; j < 8; j++) {
                const float* vp = Vt + (ks * 8 + cq) * VSTR + j * 8 + lr;
                uint32_t b0 = ((const uint32_t*)vp)[0];
                uint32_t b1 = ((const uint32_t*)vp)[4 * VSTR];
                mma_tf32(o[j], a, b0, b1);
            }
        }
        __syncthreads();
    }

    // --- finalize and write O ---
    float il0 = 1.f / l0, il1 = 1.f / l1;
    float* O0 = Og + (size_t)(q0 + wr + lr) * DIM + h * HD + 2 * cq;
    float* O1 = O0 + 8 * DIM;
    #pragma unroll
    for (int j = 0; j < 8; j++) {
        *(float2*)(O0 + j * 8) = make_float2(o[j][0] * il0, o[j][1] * il0);
        *(float2*)(O1 + j * 8) = make_float2(o[j][2] * il1, o[j][3] * il1);
    }
}

// ---------------- TF32 WMMA GEMM, cp.async double-buffered ----------------
// C = epi(A @ B), all row-major. M%128==0, N%128==0, K%32==0.
// EPI: 0 = acc + bias ; 1 = gelu(acc + bias) ; 2 = acc + bias + resid
#define ASTR 36
#define BSTR 132
#define ASTAGE (128 * ASTR)
#define BSTAGE (32 * BSTR)
template<int EPI>
__global__ void __launch_bounds__(256)
gemm_tf32_kernel(const float* __restrict__ A, const float* __restrict__ B,
                 const float* __restrict__ bias, const float* __restrict__ Rg,
                 float* __restrict__ C,
                 int M, int N, int K, int lda, int ldb, int ldc) {
    extern __shared__ float smem[];
    float* As = smem;                 // 2 stages of 128x36
    float* Bs = smem + 2 * ASTAGE;    // 2 stages of 32x132

    const int bm0 = blockIdx.y * 128;
    const int bn0 = blockIdx.x * 128;
    const int tid = threadIdx.x;
    const int warp = tid >> 5, lane = tid & 31;
    const int wm = warp & 3;
    const int wn = warp >> 2;

    wmma::fragment<wmma::accumulator, 16, 16, 8, float> acc[2][4];
    #pragma unroll
    for (int i = 0; i < 2; i++)
        #pragma unroll
        for (int j = 0; j < 4; j++) wmma::fill_fragment(acc[i][j], 0.0f);

    const int nk = K >> 5;

    // tile loader (cp.async 16B)
    auto load_tile = [&](int stage, int k0) {
        float* as = As + stage * ASTAGE;
        float* bs = Bs + stage * BSTAGE;
        #pragma unroll
        for (int t = 0; t < 4; t++) {
            int idx = tid + t * 256;          // 128 rows x 8 float4
            int r = idx >> 3, c4 = (idx & 7) * 4;
            cpa16(as + r * ASTR + c4, A + (size_t)(bm0 + r) * lda + k0 + c4);
        }
        #pragma unroll
        for (int t = 0; t < 4; t++) {
            int idx = tid + t * 256;          // 32 rows x 32 float4
            int r = idx >> 5, c4 = (idx & 31) * 4;
            cpa16(bs + r * BSTR + c4, B + (size_t)(k0 + r) * ldb + bn0 + c4);
        }
    };

    load_tile(0, 0);
    cpa_commit();

    for (int kt = 0; kt < nk; kt++) {
        if (kt + 1 < nk) {
            load_tile((kt + 1) & 1, (kt + 1) * 32);
            cpa_commit();
            cpa_wait<1>();
        } else {
            cpa_wait<0>();
        }
        __syncthreads();

        const float* as = As + (kt & 1) * ASTAGE;
        const float* bs = Bs + (kt & 1) * BSTAGE;
        #pragma unroll
        for (int kk = 0; kk < 32; kk += 8) {
            wmma::fragment<wmma::matrix_a, 16, 16, 8, tf32_t, wmma::row_major> af[2];
            wmma::fragment<wmma::matrix_b, 16, 16, 8, tf32_t, wmma::row_major> bf[4];
            #pragma unroll
            for (int i = 0; i < 2; i++) {
                wmma::load_matrix_sync(af[i], as + (wm * 32 + i * 16) * ASTR + kk, ASTR);
                #pragma unroll
                for (int t = 0; t < af[i].num_elements; t++)
                    af[i].x[t] = wmma::__float_to_tf32(af[i].x[t]);
            }
            #pragma unroll
            for (int j = 0; j < 4; j++) {
                wmma::load_matrix_sync(bf[j], bs + kk * BSTR + wn * 64 + j * 16, BSTR);
                #pragma unroll
                for (int t = 0; t < bf[j].num_elements; t++)
                    bf[j].x[t] = wmma::__float_to_tf32(bf[j].x[t]);
            }
            #pragma unroll
            for (int i = 0; i < 2; i++)
                #pragma unroll
                for (int j = 0; j < 4; j++)
                    wmma::mma_sync(acc[i][j], af[i], bf[j], acc[i][j]);
        }
        __syncthreads();
    }

    // --- epilogue: stage each 16x16 frag in reused As, then fused epi ---
    float* st = As + warp * 384;   // 16 x 24 per warp, disjoint
    #pragma unroll
    for (int i = 0; i < 2; i++) {
        #pragma unroll
        for (int j = 0; j < 4; j++) {
            wmma::store_matrix_sync(st, acc[i][j], 24, wmma::mem_row_major);
            __syncwarp();
            int rb = bm0 + wm * 32 + i * 16;
            int cb = bn0 + wn * 64 + j * 16;
            #pragma unroll
            for (int e = 0; e < 8; e++) {
                int ei = lane + e * 32;
                int r = ei >> 4, c = ei & 15;
                int gc = cb + c;
                float v = st[r * 24 + c] + bias[gc];
                if (EPI == 1) v = gelu_tanh(v);
                else if (EPI == 2) v += Rg[(size_t)(rb + r) * ldc + gc];
                C[(size_t)(rb + r) * ldc + gc] = v;
            }
            __syncwarp();
        }
    }
}

// ---------------- launch ----------------
#define GEMM_SMEM ((2 * ASTAGE + 2 * BSTAGE) * 4)
#define FLASH_SMEM ((64 * KSTR + 64 * VSTR + 128 * PSTR) * 4)

extern "C" void kernel_launch(void* const* d_in, const int* in_sizes, int n_in,
                              void* d_out, int out_size) {
    const float* x     = (const float*)d_in[0];
    const float* ctx   = (const float*)d_in[1];
    const float* wq    = (const float*)d_in[2];
    const float* bq    = (const float*)d_in[3];
    const float* wk    = (const float*)d_in[4];
    const float* bk    = (const float*)d_in[5];
    const float* wv    = (const float*)d_in[6];
    const float* bv    = (const float*)d_in[7];
    const float* wo    = (const float*)d_in[8];
    const float* bo    = (const float*)d_in[9];
    const float* w1    = (const float*)d_in[10];
    const float* b1    = (const float*)d_in[11];
    const float* w2    = (const float*)d_in[12];
    const float* b2    = (const float*)d_in[13];
    const float* qn_w  = (const float*)d_in[14];
    const float* qn_b  = (const float*)d_in[15];
    const float* kvn_w = (const float*)d_in[16];
    const float* kvn_b = (const float*)d_in[17];
    const float* pn_w  = (const float*)d_in[18];
    const float* pn_b  = (const float*)d_in[19];
    float* out = (float*)d_out;

    float *XQ, *KVN, *Q, *K, *V, *O, *X2, *HL, *H1;
    cudaGetSymbolAddress((void**)&XQ,  g_XQ);
    cudaGetSymbolAddress((void**)&KVN, g_KVN);
    cudaGetSymbolAddress((void**)&Q,   g_Q);
    cudaGetSymbolAddress((void**)&K,   g_K);
    cudaGetSymbolAddress((void**)&V,   g_V);
    cudaGetSymbolAddress((void**)&O,   g_O);
    cudaGetSymbolAddress((void**)&X2,  g_X2);
    cudaGetSymbolAddress((void**)&HL,  g_HL);
    cudaGetSymbolAddress((void**)&H1,  g_H1);

    cudaFuncSetAttribute(gemm_tf32_kernel<0>, cudaFuncAttributeMaxDynamicSharedMemorySize, GEMM_SMEM);
    cudaFuncSetAttribute(gemm_tf32_kernel<1>, cudaFuncAttributeMaxDynamicSharedMemorySize, GEMM_SMEM);
    cudaFuncSetAttribute(gemm_tf32_kernel<2>, cudaFuncAttributeMaxDynamicSharedMemorySize, GEMM_SMEM);
    cudaFuncSetAttribute(flash_kernel, cudaFuncAttributeMaxDynamicSharedMemorySize, FLASH_SMEM);

    // 1) pre-norms
    ln_kernel<<<NQ, 256>>>(x, qn_w, qn_b, XQ, DIM);
    ln_kernel<<<MCTX, 256>>>(ctx, kvn_w, kvn_b, KVN, CDIM);

    // 2) Q/K/V projections
    gemm_tf32_kernel<0><<<dim3(DIM / 128, NQ / 128), 256, GEMM_SMEM>>>(
        XQ, wq, bq, nullptr, Q, NQ, DIM, DIM, DIM, DIM, DIM);
    gemm_tf32_kernel<0><<<dim3(DIM / 128, MCTX / 128), 256, GEMM_SMEM>>>(
        KVN, wk, bk, nullptr, K, MCTX, DIM, CDIM, CDIM, DIM, DIM);
    gemm_tf32_kernel<0><<<dim3(DIM / 128, MCTX / 128), 256, GEMM_SMEM>>>(
        KVN, wv, bv, nullptr, V, MCTX, DIM, CDIM, CDIM, DIM, DIM);

    // 3) fused flash attention -> O
    flash_kernel<<<dim3(NQ / 128, HEADS), 256, FLASH_SMEM>>>(Q, K, V, O);

    // 4) output projection + residual
    gemm_tf32_kernel<2><<<dim3(DIM / 128, NQ / 128), 256, GEMM_SMEM>>>(
        O, wo, bo, x, X2, NQ, DIM, DIM, DIM, DIM, DIM);

    // 5) MLP block
    ln_kernel<<<NQ, 256>>>(X2, pn_w, pn_b, HL, DIM);
    gemm_tf32_kernel<1><<<dim3(DFF / 128, NQ / 128), 256, GEMM_SMEM>>>(
        HL, w1, b1, nullptr, H1, NQ, DFF, DIM, DIM, DFF, DFF);
    gemm_tf32_kernel<2><<<dim3(DIM / 128, NQ / 128), 256, GEMM_SMEM>>>(
        H1, w2, b2, X2, out, NQ, DIM, DFF, DFF, DIM, DIM);

    (void)in_sizes; (void)n_in; (void)out_size;
}

// round 4
// speedup vs baseline: 1.8685x; 1.0332x over previous
#include <cuda_runtime.h>
#include <cuda_bf16.h>
#include <mma.h>
#include <math.h>
#include <stdint.h>

using namespace nvcuda;
using tf32_t = wmma::precision::tf32;

// ---------------- problem constants ----------------
#define NQ   2048
#define DIM  1024
#define CDIM 768
#define HEADS 16
#define HD   64
#define MCTX 2048
#define DFF  4096

// ---------------- scratch ----------------
__device__ float g_XQ[(size_t)NQ * DIM];
__device__ float g_KVN[(size_t)MCTX * CDIM];
__device__ float g_Q[(size_t)NQ * DIM];
__device__ float g_K[(size_t)MCTX * DIM];
__device__ float g_V[(size_t)MCTX * DIM];
__device__ float g_O[(size_t)NQ * DIM];
__device__ float g_X2[(size_t)NQ * DIM];
__device__ float g_HL[(size_t)NQ * DIM];
__device__ float g_H1[(size_t)NQ * DFF];

// ---------------- helpers ----------------
__device__ __forceinline__ float gelu_tanh(float x) {
    float x3 = x * x * x;
    return 0.5f * x * (1.0f + tanhf(0.7978845608028654f * (x + 0.044715f * x3)));
}
// raw fp32 bits fed to HMMA.TF32 (hardware truncates low mantissa bits)
__device__ __forceinline__ void mma_tf32(float* d, const uint32_t* a, uint32_t b0, uint32_t b1) {
    asm volatile(
        "mma.sync.aligned.m16n8k8.row.col.f32.tf32.tf32.f32 "
        "{%0,%1,%2,%3}, {%4,%5,%6,%7}, {%8,%9}, {%0,%1,%2,%3};\n"
        : "+f"(d[0]), "+f"(d[1]), "+f"(d[2]), "+f"(d[3])
        : "r"(a[0]), "r"(a[1]), "r"(a[2]), "r"(a[3]), "r"(b0), "r"(b1));
}
__device__ __forceinline__ void cpa16(void* dst, const void* src) {
    uint32_t d = (uint32_t)__cvta_generic_to_shared(dst);
    asm volatile("cp.async.cg.shared.global [%0], [%1], 16;\n" :: "r"(d), "l"(src));
}
__device__ __forceinline__ void cpa_commit() { asm volatile("cp.async.commit_group;\n"); }
template<int N>
__device__ __forceinline__ void cpa_wait() { asm volatile("cp.async.wait_group %0;\n" :: "n"(N)); }

__device__ __forceinline__ float blockReduceSum(float v, float* red) {
    __syncthreads();
    int lane = threadIdx.x & 31, wid = threadIdx.x >> 5;
    #pragma unroll
    for (int o = 16; o > 0; o >>= 1) v += __shfl_down_sync(0xffffffffu, v, o);
    if (lane == 0) red[wid] = v;
    __syncthreads();
    int nw = blockDim.x >> 5;
    v = (threadIdx.x < nw) ? red[threadIdx.x] : 0.0f;
    if (wid == 0) {
        #pragma unroll
        for (int o = 16; o > 0; o >>= 1) v += __shfl_down_sync(0xffffffffu, v, o);
    }
    return v;
}

// ---------------- layernorm ----------------
__global__ void ln_kernel(const float* __restrict__ in, const float* __restrict__ w,
                          const float* __restrict__ b, float* __restrict__ out, int D) {
    int row = blockIdx.x;
    const float* r = in + (size_t)row * D;
    float* o = out + (size_t)row * D;
    __shared__ float red[32];
    __shared__ float s_mean, s_inv;
    int tid = threadIdx.x;

    float s = 0.f;
    for (int i = tid; i < D; i += blockDim.x) s += r[i];
    s = blockReduceSum(s, red);
    if (tid == 0) s_mean = s / (float)D;
    __syncthreads();
    float mean = s_mean;

    float v = 0.f;
    for (int i = tid; i < D; i += blockDim.x) { float c = r[i] - mean; v += c * c; }
    v = blockReduceSum(v, red);
    if (tid == 0) s_inv = rsqrtf(v / (float)D + 1e-12f);
    __syncthreads();
    float inv = s_inv;

    for (int i = tid; i < D; i += blockDim.x)
        o[i] = (r[i] - mean) * inv * w[i] + b[i];
}

// ---------------- fused flash attention (TF32 mma.sync, cp.async 2-stage) ----------------
// grid (NQ/128, HEADS), 256 threads. Warp owns 16 query rows. KV chunk = 64 tokens.
#define KSTR 68
#define VSTR 72
#define PSTR 68
#define KV_STG (64 * KSTR + 64 * VSTR)      // floats per stage
#define FLASH_SMEM ((2 * KV_STG + 128 * PSTR) * 4)
__global__ void __launch_bounds__(256)
flash_kernel(const float* __restrict__ Qg, const float* __restrict__ Kg,
             const float* __restrict__ Vg, float* __restrict__ Og) {
    extern __shared__ float sm[];
    float* Ps = sm + 2 * KV_STG;

    const int h = blockIdx.y;
    const int q0 = blockIdx.x * 128;
    const int tid = threadIdx.x;
    const int w = tid >> 5, lane = tid & 31;
    const int lr = lane >> 2;      // 0..7
    const int cq = lane & 3;       // 0..3
    const int wr = w * 16;

    // Q fragments, pre-scaled; raw bits (tf32 truncation in HW)
    uint32_t qa[8][4];
    {
        const float* Qb = Qg + (size_t)(q0 + wr + lr) * DIM + h * HD;
        const float* Qb8 = Qb + 8 * DIM;
        #pragma unroll
        for (int ks = 0; ks < 8; ks++) {
            int c = ks * 8 + cq;
            qa[ks][0] = __float_as_uint(Qb [c]     * 0.125f);
            qa[ks][1] = __float_as_uint(Qb8[c]     * 0.125f);
            qa[ks][2] = __float_as_uint(Qb [c + 4] * 0.125f);
            qa[ks][3] = __float_as_uint(Qb8[c + 4] * 0.125f);
        }
    }

    float o[8][4];
    #pragma unroll
    for (int j = 0; j < 8; j++)
        #pragma unroll
        for (int e = 0; e < 4; e++) o[j][e] = 0.f;
    float m0 = -1e30f, m1 = -1e30f, l0 = 0.f, l1 = 0.f;

    // chunk loader: 64x64 K and V, float4 cp.async
    auto load_chunk = [&](int stage, int c0) {
        float* Kt = sm + stage * KV_STG;
        float* Vt = Kt + 64 * KSTR;
        #pragma unroll
        for (int t = 0; t < 4; t++) {
            int idx = tid + t * 256;
            int r = idx >> 4, c4 = (idx & 15) * 4;
            cpa16(Kt + r * KSTR + c4, Kg + (size_t)(c0 + r) * DIM + h * HD + c4);
            cpa16(Vt + r * VSTR + c4, Vg + (size_t)(c0 + r) * DIM + h * HD + c4);
        }
    };

    load_chunk(0, 0);
    cpa_commit();

    const int nchunks = MCTX / 64;
    for (int ci = 0; ci < nchunks; ci++) {
        if (ci + 1 < nchunks) {
            load_chunk((ci + 1) & 1, (ci + 1) * 64);
            cpa_commit();
            cpa_wait<1>();
        } else {
            cpa_wait<0>();
        }
        __syncthreads();

        const float* Kt = sm + (ci & 1) * KV_STG;
        const float* Vt = Kt + 64 * KSTR;

        // S = Q @ K^T
        float s[8][4];
        #pragma unroll
        for (int j = 0; j < 8; j++)
            #pragma unroll
            for (int e = 0; e < 4; e++) s[j][e] = 0.f;

        #pragma unroll
        for (int ks = 0; ks < 8; ks++) {
            #pragma unroll
            for (int j = 0; j < 8; j++) {
                const float* kp = Kt + (j * 8 + lr) * KSTR + ks * 8 + cq;
                uint32_t b0 = ((const uint32_t*)kp)[0];
                uint32_t b1 = ((const uint32_t*)kp)[4];
                mma_tf32(s[j], qa[ks], b0, b1);
            }
        }

        // online softmax
        float mx0 = -1e30f, mx1 = -1e30f;
        #pragma unroll
        for (int j = 0; j < 8; j++) {
            mx0 = fmaxf(mx0, fmaxf(s[j][0], s[j][1]));
            mx1 = fmaxf(mx1, fmaxf(s[j][2], s[j][3]));
        }
        #pragma unroll
        for (int d = 1; d < 4; d <<= 1) {
            mx0 = fmaxf(mx0, __shfl_xor_sync(0xffffffffu, mx0, d));
            mx1 = fmaxf(mx1, __shfl_xor_sync(0xffffffffu, mx1, d));
        }
        float mn0 = fmaxf(m0, mx0), mn1 = fmaxf(m1, mx1);
        float cr0 = __expf(m0 - mn0), cr1 = __expf(m1 - mn1);
        float sum0 = 0.f, sum1 = 0.f;
        #pragma unroll
        for (int j = 0; j < 8; j++) {
            s[j][0] = __expf(s[j][0] - mn0); sum0 += s[j][0];
            s[j][1] = __expf(s[j][1] - mn0); sum0 += s[j][1];
            s[j][2] = __expf(s[j][2] - mn1); sum1 += s[j][2];
            s[j][3] = __expf(s[j][3] - mn1); sum1 += s[j][3];
        }
        #pragma unroll
        for (int d = 1; d < 4; d <<= 1) {
            sum0 += __shfl_xor_sync(0xffffffffu, sum0, d);
            sum1 += __shfl_xor_sync(0xffffffffu, sum1, d);
        }
        l0 = l0 * cr0 + sum0;
        l1 = l1 * cr1 + sum1;
        m0 = mn0; m1 = mn1;
        #pragma unroll
        for (int j = 0; j < 8; j++) {
            o[j][0] *= cr0; o[j][1] *= cr0;
            o[j][2] *= cr1; o[j][3] *= cr1;
        }

        // stash P (raw floats) into warp-private smem
        {
            float* p0 = Ps + (wr + lr) * PSTR + 2 * cq;
            float* p1 = Ps + (wr + lr + 8) * PSTR + 2 * cq;
            #pragma unroll
            for (int j = 0; j < 8; j++) {
                p0[j * 8 + 0] = s[j][0];
                p0[j * 8 + 1] = s[j][1];
                p1[j * 8 + 0] = s[j][2];
                p1[j * 8 + 1] = s[j][3];
            }
        }
        __syncwarp();

        // O += P @ V
        #pragma unroll
        for (int ks = 0; ks < 8; ks++) {
            uint32_t a[4];
            const float* pa = Ps + (wr + lr) * PSTR + ks * 8 + cq;
            a[0] = ((const uint32_t*)pa)[0];
            a[1] = ((const uint32_t*)pa)[8 * PSTR];
            a[2] = ((const uint32_t*)pa)[4];
            a[3] = ((const uint32_t*)pa)[8 * PSTR + 4];
            #pragma unroll
            for (int j = 0; j < 8; j++) {
                const float* vp = Vt + (ks * 8 + cq) * VSTR + j * 8 + lr;
                uint32_t b0 = ((const uint32_t*)vp)[0];
                uint32_t b1 = ((const uint32_t*)vp)[4 * VSTR];
                mma_tf32(o[j], a, b0, b1);
            }
        }
        __syncthreads();
    }

    float il0 = 1.f / l0, il1 = 1.f / l1;
    float* O0 = Og + (size_t)(q0 + wr + lr) * DIM + h * HD + 2 * cq;
    float* O1 = O0 + 8 * DIM;
    #pragma unroll
    for (int j = 0; j < 8; j++) {
        *(float2*)(O0 + j * 8) = make_float2(o[j][0] * il0, o[j][1] * il0);
        *(float2*)(O1 + j * 8) = make_float2(o[j][2] * il1, o[j][3] * il1);
    }
}

// ---------------- TF32 WMMA GEMM, cp.async double-buffered, 2 CTA/SM ----------------
// C = epi(A @ B), row-major. M%128==0, N%128==0, K%32==0.
// EPI: 0 = +bias ; 1 = gelu(+bias) ; 2 = +bias+resid
#define ASTR 36
#define BSTR 132
#define ASTAGE (128 * ASTR)
#define BSTAGE (32 * BSTR)
#define GEMM_SMEM ((2 * ASTAGE + 2 * BSTAGE) * 4)
template<int EPI>
__global__ void __launch_bounds__(256, 2)
gemm_tf32_kernel(const float* __restrict__ A, const float* __restrict__ B,
                 const float* __restrict__ bias, const float* __restrict__ Rg,
                 float* __restrict__ C,
                 int M, int N, int K, int lda, int ldb, int ldc) {
    extern __shared__ float smem[];
    float* As = smem;
    float* Bs = smem + 2 * ASTAGE;

    const int bm0 = blockIdx.y * 128;
    const int bn0 = blockIdx.x * 128;
    const int tid = threadIdx.x;
    const int warp = tid >> 5, lane = tid & 31;
    const int wm = warp & 3;
    const int wn = warp >> 2;

    wmma::fragment<wmma::accumulator, 16, 16, 8, float> acc[2][4];
    #pragma unroll
    for (int i = 0; i < 2; i++)
        #pragma unroll
        for (int j = 0; j < 4; j++) wmma::fill_fragment(acc[i][j], 0.0f);

    const int nk = K >> 5;

    auto load_tile = [&](int stage, int k0) {
        float* as = As + stage * ASTAGE;
        float* bs = Bs + stage * BSTAGE;
        #pragma unroll
        for (int t = 0; t < 4; t++) {
            int idx = tid + t * 256;
            int r = idx >> 3, c4 = (idx & 7) * 4;
            cpa16(as + r * ASTR + c4, A + (size_t)(bm0 + r) * lda + k0 + c4);
        }
        #pragma unroll
        for (int t = 0; t < 4; t++) {
            int idx = tid + t * 256;
            int r = idx >> 5, c4 = (idx & 31) * 4;
            cpa16(bs + r * BSTR + c4, B + (size_t)(k0 + r) * ldb + bn0 + c4);
        }
    };

    load_tile(0, 0);
    cpa_commit();

    for (int kt = 0; kt < nk; kt++) {
        if (kt + 1 < nk) {
            load_tile((kt + 1) & 1, (kt + 1) * 32);
            cpa_commit();
            cpa_wait<1>();
        } else {
            cpa_wait<0>();
        }
        __syncthreads();

        const float* as = As + (kt & 1) * ASTAGE;
        const float* bs = Bs + (kt & 1) * BSTAGE;
        #pragma unroll
        for (int kk = 0; kk < 32; kk += 8) {
            wmma::fragment<wmma::matrix_a, 16, 16, 8, tf32_t, wmma::row_major> af[2];
            wmma::fragment<wmma::matrix_b, 16, 16, 8, tf32_t, wmma::row_major> bf[4];
            #pragma unroll
            for (int i = 0; i < 2; i++)
                wmma::load_matrix_sync(af[i], as + (wm * 32 + i * 16) * ASTR + kk, ASTR);
            #pragma unroll
            for (int j = 0; j < 4; j++)
                wmma::load_matrix_sync(bf[j], bs + kk * BSTR + wn * 64 + j * 16, BSTR);
            // no explicit tf32 cvt: HMMA.TF32 truncates fp32 mantissa in HW
            #pragma unroll
            for (int i = 0; i < 2; i++)
                #pragma unroll
                for (int j = 0; j < 4; j++)
                    wmma::mma_sync(acc[i][j], af[i], bf[j], acc[i][j]);
        }
        __syncthreads();
    }

    // epilogue via reused As staging
    float* st = As + warp * 384;
    #pragma unroll
    for (int i = 0; i < 2; i++) {
        #pragma unroll
        for (int j = 0; j < 4; j++) {
            wmma::store_matrix_sync(st, acc[i][j], 24, wmma::mem_row_major);
            __syncwarp();
            int rb = bm0 + wm * 32 + i * 16;
            int cb = bn0 + wn * 64 + j * 16;
            #pragma unroll
            for (int e = 0; e < 8; e++) {
                int ei = lane + e * 32;
                int r = ei >> 4, c = ei & 15;
                int gc = cb + c;
                float v = st[r * 24 + c] + bias[gc];
                if (EPI == 1) v = gelu_tanh(v);
                else if (EPI == 2) v += Rg[(size_t)(rb + r) * ldc + gc];
                C[(size_t)(rb + r) * ldc + gc] = v;
            }
            __syncwarp();
        }
    }
}

// ---------------- launch ----------------
extern "C" void kernel_launch(void* const* d_in, const int* in_sizes, int n_in,
                              void* d_out, int out_size) {
    const float* x     = (const float*)d_in[0];
    const float* ctx   = (const float*)d_in[1];
    const float* wq    = (const float*)d_in[2];
    const float* bq    = (const float*)d_in[3];
    const float* wk    = (const float*)d_in[4];
    const float* bk    = (const float*)d_in[5];
    const float* wv    = (const float*)d_in[6];
    const float* bv    = (const float*)d_in[7];
    const float* wo    = (const float*)d_in[8];
    const float* bo    = (const float*)d_in[9];
    const float* w1    = (const float*)d_in[10];
    const float* b1    = (const float*)d_in[11];
    const float* w2    = (const float*)d_in[12];
    const float* b2    = (const float*)d_in[13];
    const float* qn_w  = (const float*)d_in[14];
    const float* qn_b  = (const float*)d_in[15];
    const float* kvn_w = (const float*)d_in[16];
    const float* kvn_b = (const float*)d_in[17];
    const float* pn_w  = (const float*)d_in[18];
    const float* pn_b  = (const float*)d_in[19];
    float* out = (float*)d_out;

    float *XQ, *KVN, *Q, *K, *V, *O, *X2, *HL, *H1;
    cudaGetSymbolAddress((void**)&XQ,  g_XQ);
    cudaGetSymbolAddress((void**)&KVN, g_KVN);
    cudaGetSymbolAddress((void**)&Q,   g_Q);
    cudaGetSymbolAddress((void**)&K,   g_K);
    cudaGetSymbolAddress((void**)&V,   g_V);
    cudaGetSymbolAddress((void**)&O,   g_O);
    cudaGetSymbolAddress((void**)&X2,  g_X2);
    cudaGetSymbolAddress((void**)&HL,  g_HL);
    cudaGetSymbolAddress((void**)&H1,  g_H1);

    cudaFuncSetAttribute(gemm_tf32_kernel<0>, cudaFuncAttributeMaxDynamicSharedMemorySize, GEMM_SMEM);
    cudaFuncSetAttribute(gemm_tf32_kernel<1>, cudaFuncAttributeMaxDynamicSharedMemorySize, GEMM_SMEM);
    cudaFuncSetAttribute(gemm_tf32_kernel<2>, cudaFuncAttributeMaxDynamicSharedMemorySize, GEMM_SMEM);
    cudaFuncSetAttribute(flash_kernel, cudaFuncAttributeMaxDynamicSharedMemorySize, FLASH_SMEM);

    // 1) pre-norms
    ln_kernel<<<NQ, 256>>>(x, qn_w, qn_b, XQ, DIM);
    ln_kernel<<<MCTX, 256>>>(ctx, kvn_w, kvn_b, KVN, CDIM);

    // 2) Q/K/V projections
    gemm_tf32_kernel<0><<<dim3(DIM / 128, NQ / 128), 256, GEMM_SMEM>>>(
        XQ, wq, bq, nullptr, Q, NQ, DIM, DIM, DIM, DIM, DIM);
    gemm_tf32_kernel<0><<<dim3(DIM / 128, MCTX / 128), 256, GEMM_SMEM>>>(
        KVN, wk, bk, nullptr, K, MCTX, DIM, CDIM, CDIM, DIM, DIM);
    gemm_tf32_kernel<0><<<dim3(DIM / 128, MCTX / 128), 256, GEMM_SMEM>>>(
        KVN, wv, bv, nullptr, V, MCTX, DIM, CDIM, CDIM, DIM, DIM);

    // 3) fused flash attention
    flash_kernel<<<dim3(NQ / 128, HEADS), 256, FLASH_SMEM>>>(Q, K, V, O);

    // 4) output projection + residual
    gemm_tf32_kernel<2><<<dim3(DIM / 128, NQ / 128), 256, GEMM_SMEM>>>(
        O, wo, bo, x, X2, NQ, DIM, DIM, DIM, DIM, DIM);

    // 5) MLP
    ln_kernel<<<NQ, 256>>>(X2, pn_w, pn_b, HL, DIM);
    gemm_tf32_kernel<1><<<dim3(DFF / 128, NQ / 128), 256, GEMM_SMEM>>>(
        HL, w1, b1, nullptr, H1, NQ, DFF, DIM, DIM, DFF, DFF);
    gemm_tf32_kernel<2><<<dim3(DIM / 128, NQ / 128), 256, GEMM_SMEM>>>(
        H1, w2, b2, X2, out, NQ, DIM, DFF, DFF, DIM, DIM);

    (void)in_sizes; (void)n_in; (void)out_size;
}